// round 15
// baseline (speedup 1.0000x reference)
#include <cuda_runtime.h>

// Problem constants
#define BB 2
#define CC 128
#define GG 8
#define CG 16
#define HH 64
#define WW 64

// Attention tile: 8 rows x 16 cols. Corner-trimmed halo: 500 slots.
#define TH 8
#define TW 16
#define NS 500
#define KVF (NS*CG)                      // 8000 floats per map
#define SMEM_FLOATS (2*KVF + 32 + 112)
#define SMEM_BYTES (SMEM_FLOATS*4)       // 64,576 B -> 3 blocks/SM

#define L2E 1.4426950408889634f

// Scratch maps in [b][oc][pix] layout (coalesced GEMM epilogue)
__device__ float g_q[BB*CC*HH*WW];
__device__ float g_k[BB*CC*HH*WW];
__device__ float g_v[BB*CC*HH*WW];

typedef unsigned long long ull;
__device__ __forceinline__ ull pk2(float lo, float hi) {
    ull r; asm("mov.b64 %0, {%1, %2};" : "=l"(r) : "f"(lo), "f"(hi)); return r;
}
__device__ __forceinline__ void upk2(ull v, float& lo, float& hi) {
    asm("mov.b64 {%0, %1}, %2;" : "=f"(lo), "=f"(hi) : "l"(v));
}
__device__ __forceinline__ void fma2(ull& d, ull a, ull b) {
    asm("fma.rn.f32x2 %0, %1, %2, %0;" : "+l"(d) : "l"(a), "l"(b));
}
__device__ __forceinline__ void mul2(ull& d, ull a, ull b) {
    asm("mul.rn.f32x2 %0, %1, %2;" : "=l"(d) : "l"(a), "l"(b));
}
__device__ __forceinline__ ull add2(ull a, ull b) {
    ull r; asm("add.rn.f32x2 %0, %1, %2;" : "=l"(r) : "l"(a), "l"(b)); return r;
}
__device__ __forceinline__ float ex2(float x) {
    float r; asm("ex2.approx.f32 %0, %1;" : "=f"(r) : "f"(x)); return r;
}

// ---------------------------------------------------------------------------
// Kernel 1: Q/K/V 1x1 conv GEMM — exact R2 version (proven ~13us).
// grid.z: 0=Q(from fm[:,128:]), 1=K, 2=V. 256 thr, 64 pixels x 128 oc.
// ---------------------------------------------------------------------------
__global__ __launch_bounds__(256) void qkv_gemm(
    const float* __restrict__ fm,
    const float* __restrict__ wq,
    const float* __restrict__ wk,
    const float* __restrict__ wv)
{
    __shared__ float wS[128][33];   // [oc][kk], padded
    __shared__ float xS[32][64];    // [kk][pixel]

    int z = blockIdx.z;
    const float* w  = (z == 0) ? wq : (z == 1 ? wk : wv);
    float*       op = (z == 0) ? g_q : (z == 1 ? g_k : g_v);
    int coff        = (z == 0) ? 128 : 0;

    int t    = threadIdx.x;
    int pix0 = blockIdx.x * 64;
    int b    = pix0 >> 12;
    int rem0 = pix0 & 4095;

    const float* xbase = fm + ((size_t)(b * 256 + coff) << 12) + rem0;

    int ocb = (t >> 4) << 3;               // 0..120 step 8
    int pxb = (t & 15) << 2;               // 0..60 step 4

    float acc[8][4];
#pragma unroll
    for (int u = 0; u < 8; u++)
#pragma unroll
        for (int p = 0; p < 4; p++) acc[u][p] = 0.f;

    for (int ic0 = 0; ic0 < 128; ic0 += 32) {
#pragma unroll
        for (int j = 0; j < 16; j++) {
            int idx = t + j * 256;
            wS[idx >> 5][idx & 31] = w[(idx >> 5) * 128 + ic0 + (idx & 31)];
        }
#pragma unroll
        for (int j = 0; j < 8; j++) {
            int idx = t + j * 256;
            xS[idx >> 6][idx & 63] =
                xbase[(size_t)(ic0 + (idx >> 6)) * 4096 + (idx & 63)];
        }
        __syncthreads();

#pragma unroll
        for (int kk = 0; kk < 32; kk++) {
            float x0 = xS[kk][pxb + 0];
            float x1 = xS[kk][pxb + 1];
            float x2 = xS[kk][pxb + 2];
            float x3 = xS[kk][pxb + 3];
#pragma unroll
            for (int u = 0; u < 8; u++) {
                float wv_ = wS[ocb + u][kk];
                acc[u][0] += wv_ * x0;
                acc[u][1] += wv_ * x1;
                acc[u][2] += wv_ * x2;
                acc[u][3] += wv_ * x3;
            }
        }
        __syncthreads();
    }

    float* ob = op + ((size_t)b << 19) + rem0;   // b*128*4096
#pragma unroll
    for (int u = 0; u < 8; u++) {
        float4 v = make_float4(acc[u][0], acc[u][1], acc[u][2], acc[u][3]);
        *(float4*)(ob + (size_t)(ocb + u) * 4096 + pxb) = v;
    }
}

// ---------------------------------------------------------------------------
// Kernel 2: fused windowed attention. 8x16 tile, 128 threads, 1 thread/px,
// 3 blocks/SM. 500-slot corner-trimmed halo in quad-plane smem layout
// (conflict-free LDS.128). Row-base LUT: slot = lut[r+7] + c, r in [-7,14].
//   rows -7..-4 : cols [0,15]  base 0      (col strip)
//   rows -3..-1 : cols [-3,18] base 64     (main rows above tile)
//   rows  0..7  : cols [-7,22] base 130    (full width)
//   rows  8..10 : cols [-3,18] base 370
//   rows 11..14 : cols [0,15]  base 436
// ---------------------------------------------------------------------------
__global__ __launch_bounds__(128, 3) void attn_kernel(
    const float* __restrict__ relh,
    const float* __restrict__ relw,
    float* __restrict__ out)
{
    extern __shared__ float sh[];
    float* Ks   = sh;                     // 4 planes x NS x 4 floats
    float* Vs   = sh + KVF;
    int*   lutS = (int*)(sh + 2 * KVF);   // 32 ints
    float* relS = sh + 2 * KVF + 32;      // 112 floats

    int tid = threadIdx.x;
    int bz  = blockIdx.z;
    int b   = bz >> 3;
    int g   = bz & 7;
    int h0  = blockIdx.y * TH;
    int w0  = blockIdx.x * TW;

    // group channel base in [b][oc][pix] layout
    const float* Kg = g_k + ((size_t)(b * CC + g * CG) << 12);
    const float* Vg = g_v + ((size_t)(b * CC + g * CG) << 12);

    if (tid < 22) {
        int r = tid - 7;
        int v;
        if (r < -3)      v = (r + 7) * 16;
        else if (r < 0)  v = 64  + (r + 3) * 22 + 3;
        else if (r < 8)  v = 130 + r * 30 + 7;
        else if (r < 11) v = 370 + (r - 8) * 22 + 3;
        else             v = 436 + (r - 11) * 16;
        lutS[tid] = v;
    }
    if (tid < 112)
        relS[tid] = (g < 4) ? relh[g * 112 + tid] : relw[(g - 4) * 112 + tid];

    // Halo fill: per channel-plane, 4 coalesced scalar-LDG rounds + STS.128.
#pragma unroll
    for (int q = 0; q < 4; q++) {
        const float* kq = Kg + (size_t)(q * 4) * 4096;
        const float* vq = Vg + (size_t)(q * 4) * 4096;
        for (int s = tid; s < NS; s += 128) {
            int r, c;
            if (s < 64)       { r = -7 + (s >> 4); c = s & 15; }
            else if (s < 130) { int t2 = s - 64;  int rr = t2 / 22; r = -3 + rr; c = t2 - rr * 22 - 3; }
            else if (s < 370) { int t2 = s - 130; int rr = t2 / 30; r = rr;      c = t2 - rr * 30 - 7; }
            else if (s < 436) { int t2 = s - 370; int rr = t2 / 22; r = 8 + rr;  c = t2 - rr * 22 - 3; }
            else              { int t2 = s - 436; r = 11 + (t2 >> 4); c = t2 & 15; }
            int gh = h0 + r, gw = w0 + c;
            float k0 = 0.f, k1 = 0.f, k2 = 0.f, k3 = 0.f;
            float v0 = 0.f, v1 = 0.f, v2 = 0.f, v3 = 0.f;
            if ((unsigned)gh < HH && (unsigned)gw < WW) {
                int pix = (gh << 6) + gw;
                k0 = kq[pix]; k1 = kq[pix + 4096]; k2 = kq[pix + 2*4096]; k3 = kq[pix + 3*4096];
                v0 = vq[pix]; v1 = vq[pix + 4096]; v2 = vq[pix + 2*4096]; v3 = vq[pix + 3*4096];
            }
            *(float4*)(Ks + (q * NS + s) * 4) = make_float4(k0, k1, k2, k3);
            *(float4*)(Vs + (q * NS + s) * 4) = make_float4(v0, v1, v2, v3);
        }
    }
    __syncthreads();

    int row = tid >> 4, col = tid & 15;
    int h = h0 + row, w = w0 + col;

    // q (16 ch) from [oc][pix], pre-scaled by log2(e)
    const float* qp = g_q + ((size_t)(b * CC + g * CG) << 12) + (h << 6) + w;
    float qs[16];
#pragma unroll
    for (int c = 0; c < 16; c++) qs[c] = qp[(size_t)c * 4096] * L2E;

    float bias[7];
#pragma unroll
    for (int i = 0; i < 7; i++) {
        float bsum = 0.f;
#pragma unroll
        for (int c = 0; c < 16; c++)
            bsum = fmaf(qs[c], relS[c * 7 + i], bsum);
        bias[i] = bsum;
    }

    ull q2[8];
#pragma unroll
    for (int i = 0; i < 8; i++) q2[i] = pk2(qs[2*i], qs[2*i+1]);

    bool gh4 = (g < 4);

    // ---- Main 7x7 window ----
    float s0 = 0.f, s1 = 0.f;
    ull o[8];
#pragma unroll
    for (int i = 0; i < 8; i++) o[i] = pk2(0.f, 0.f);

#pragma unroll
    for (int di = 0; di < 7; di++) {
        int sb = lutS[row + 4 + di] + (col - 3);
#pragma unroll
        for (int dj = 0; dj < 7; dj++) {
            int sl = sb + dj;
            const float* kp = Ks + sl * 4;
            ulonglong2 k0 = *(const ulonglong2*)(kp);
            ulonglong2 k1 = *(const ulonglong2*)(kp + 1*NS*4);
            ulonglong2 k2 = *(const ulonglong2*)(kp + 2*NS*4);
            ulonglong2 k3 = *(const ulonglong2*)(kp + 3*NS*4);
            float bb = gh4 ? bias[di] : bias[dj];
            ull a0 = pk2(bb, 0.f), a1 = pk2(0.f, 0.f);
            fma2(a0, q2[0], k0.x); fma2(a1, q2[1], k0.y);
            fma2(a0, q2[2], k1.x); fma2(a1, q2[3], k1.y);
            fma2(a0, q2[4], k2.x); fma2(a1, q2[5], k2.y);
            fma2(a0, q2[6], k3.x); fma2(a1, q2[7], k3.y);
            float lo, hi; upk2(add2(a0, a1), lo, hi);
            float e = ex2(lo + hi);
            if (dj & 1) s1 += e; else s0 += e;
            ull ep = pk2(e, e);
            const float* vp = Vs + sl * 4;
            ulonglong2 v0 = *(const ulonglong2*)(vp);
            ulonglong2 v1 = *(const ulonglong2*)(vp + 1*NS*4);
            ulonglong2 v2 = *(const ulonglong2*)(vp + 2*NS*4);
            ulonglong2 v3 = *(const ulonglong2*)(vp + 3*NS*4);
            fma2(o[0], ep, v0.x); fma2(o[1], ep, v0.y);
            fma2(o[2], ep, v1.x); fma2(o[3], ep, v1.y);
            fma2(o[4], ep, v2.x); fma2(o[5], ep, v2.y);
            fma2(o[6], ep, v3.x); fma2(o[7], ep, v3.y);
        }
    }
    {
        float inv = 1.f / (s0 + s1);
        ull ip = pk2(inv, inv);
#pragma unroll
        for (int i = 0; i < 8; i++) mul2(o[i], o[i], ip);
    }

    // ---- Refine passes: row (h fixed) then col (w fixed), no bias ----
#pragma unroll
    for (int pass = 0; pass < 2; pass++) {
        float sr = 0.f;
        ull r8[8];
#pragma unroll
        for (int i = 0; i < 8; i++) r8[i] = pk2(0.f, 0.f);
        int rowBase = lutS[row + 7] + (col - 7);
#pragma unroll
        for (int j = 0; j < 15; j++) {
            int sl = (pass == 0) ? (rowBase + j) : (lutS[row + j] + col);
            const float* kp = Ks + sl * 4;
            ulonglong2 k0 = *(const ulonglong2*)(kp);
            ulonglong2 k1 = *(const ulonglong2*)(kp + 1*NS*4);
            ulonglong2 k2 = *(const ulonglong2*)(kp + 2*NS*4);
            ulonglong2 k3 = *(const ulonglong2*)(kp + 3*NS*4);
            ull a0 = pk2(0.f, 0.f), a1 = a0;
            fma2(a0, q2[0], k0.x); fma2(a1, q2[1], k0.y);
            fma2(a0, q2[2], k1.x); fma2(a1, q2[3], k1.y);
            fma2(a0, q2[4], k2.x); fma2(a1, q2[5], k2.y);
            fma2(a0, q2[6], k3.x); fma2(a1, q2[7], k3.y);
            float lo, hi; upk2(add2(a0, a1), lo, hi);
            float e = ex2(lo + hi);
            sr += e;
            ull ep = pk2(e, e);
            const float* vp = Vs + sl * 4;
            ulonglong2 v0 = *(const ulonglong2*)(vp);
            ulonglong2 v1 = *(const ulonglong2*)(vp + 1*NS*4);
            ulonglong2 v2 = *(const ulonglong2*)(vp + 2*NS*4);
            ulonglong2 v3 = *(const ulonglong2*)(vp + 3*NS*4);
            fma2(r8[0], ep, v0.x); fma2(r8[1], ep, v0.y);
            fma2(r8[2], ep, v1.x); fma2(r8[3], ep, v1.y);
            fma2(r8[4], ep, v2.x); fma2(r8[5], ep, v2.y);
            fma2(r8[6], ep, v3.x); fma2(r8[7], ep, v3.y);
        }
        float ir = 1.f / sr;
        ull ip = pk2(ir, ir);
#pragma unroll
        for (int i = 0; i < 8; i++) fma2(o[i], ip, r8[i]);
    }

    // Output: standard [b][oc][h][w], coalesced scalar stores
    size_t ob = ((size_t)(b * CC + g * CG) << 12) + (h << 6) + w;
#pragma unroll
    for (int i = 0; i < 8; i++) {
        float lo, hi; upk2(o[i], lo, hi);
        out[ob + (size_t)(2*i)     * 4096] = lo;
        out[ob + (size_t)(2*i + 1) * 4096] = hi;
    }
}

// ---------------------------------------------------------------------------
extern "C" void kernel_launch(void* const* d_in, const int* in_sizes, int n_in,
                              void* d_out, int out_size)
{
    const float* fm = (const float*)d_in[0];
    const float* wq = (const float*)d_in[1];
    const float* wk = (const float*)d_in[2];
    const float* wv = (const float*)d_in[3];
    const float* rh = (const float*)d_in[4];
    const float* rw = (const float*)d_in[5];
    float* out = (float*)d_out;

    cudaFuncSetAttribute(attn_kernel,
                         cudaFuncAttributeMaxDynamicSharedMemorySize, SMEM_BYTES);

    dim3 g1(128, 1, 3);                    // z = Q/K/V
    qkv_gemm<<<g1, 256>>>(fm, wq, wk, wv);

    dim3 g2(WW / TW, HH / TH, BB * GG);    // (4, 8, 16) = 512 blocks
    attn_kernel<<<g2, 128, SMEM_BYTES>>>(rh, rw, out);
}